// round 7
// baseline (speedup 1.0000x reference)
#include <cuda_runtime.h>

// GEMV: y = alpha * (A @ x) + beta * b
// A: [16384,16384] f32. 256-bit loads (sm_100+ LDG.E.256) for A: halves LDG
// count, doubles bytes-in-flight per outstanding load at the same reg budget.
// TPB=256, RPB=2, launch_bounds(256,8) -> 32 regs, ~100%% occ.

#define ROWS 16384
#define COLS 16384
#define TPB  256
#define RPB  2

struct __align__(32) f8 { float v[8]; };

__device__ __forceinline__ f8 ldg256(const float* p) {
    f8 r;
#if __CUDA_ARCH__ >= 1000
    asm volatile("ld.global.v8.f32 {%0,%1,%2,%3,%4,%5,%6,%7}, [%8];"
                 : "=f"(r.v[0]), "=f"(r.v[1]), "=f"(r.v[2]), "=f"(r.v[3]),
                   "=f"(r.v[4]), "=f"(r.v[5]), "=f"(r.v[6]), "=f"(r.v[7])
                 : "l"(p));
#else
    float4 a = reinterpret_cast<const float4*>(p)[0];
    float4 b = reinterpret_cast<const float4*>(p)[1];
    r.v[0]=a.x; r.v[1]=a.y; r.v[2]=a.z; r.v[3]=a.w;
    r.v[4]=b.x; r.v[5]=b.y; r.v[6]=b.z; r.v[7]=b.w;
#endif
    return r;
}

__global__ __launch_bounds__(TPB, 8) void gemv_kernel(
    const float* __restrict__ alpha,
    const float* __restrict__ A,
    const float* __restrict__ x,
    const float* __restrict__ beta,
    const float* __restrict__ b,
    float* __restrict__ y)
{
    const int row0 = blockIdx.x * RPB;
    const int tid  = threadIdx.x;

    const float* __restrict__ r0 = A + (size_t)row0 * COLS;
    const float* __restrict__ r1 = A + (size_t)(row0 + 1) * COLS;
    const float4* __restrict__ xv = reinterpret_cast<const float4*>(x);

    float acc0 = 0.0f, acc1 = 0.0f;

    // COLS/8 = 2048 f8 per row; 256 threads -> 8 iterations each.
    #pragma unroll 2
    for (int i = tid; i < COLS / 8; i += TPB) {
        f8 a0 = ldg256(r0 + 8 * (size_t)i);
        f8 a1 = ldg256(r1 + 8 * (size_t)i);
        float4 v0 = __ldg(&xv[2 * i]);
        float4 v1 = __ldg(&xv[2 * i + 1]);
        acc0 = fmaf(a0.v[0], v0.x, acc0); acc0 = fmaf(a0.v[1], v0.y, acc0);
        acc0 = fmaf(a0.v[2], v0.z, acc0); acc0 = fmaf(a0.v[3], v0.w, acc0);
        acc0 = fmaf(a0.v[4], v1.x, acc0); acc0 = fmaf(a0.v[5], v1.y, acc0);
        acc0 = fmaf(a0.v[6], v1.z, acc0); acc0 = fmaf(a0.v[7], v1.w, acc0);
        acc1 = fmaf(a1.v[0], v0.x, acc1); acc1 = fmaf(a1.v[1], v0.y, acc1);
        acc1 = fmaf(a1.v[2], v0.z, acc1); acc1 = fmaf(a1.v[3], v0.w, acc1);
        acc1 = fmaf(a1.v[4], v1.x, acc1); acc1 = fmaf(a1.v[5], v1.y, acc1);
        acc1 = fmaf(a1.v[6], v1.z, acc1); acc1 = fmaf(a1.v[7], v1.w, acc1);
    }

    // warp reduce both accumulators
    #pragma unroll
    for (int off = 16; off > 0; off >>= 1) {
        acc0 += __shfl_xor_sync(0xFFFFFFFFu, acc0, off);
        acc1 += __shfl_xor_sync(0xFFFFFFFFu, acc1, off);
    }

    __shared__ float warp_sums[RPB][TPB / 32];
    const int lane = tid & 31;
    const int wid  = tid >> 5;
    if (lane == 0) {
        warp_sums[0][wid] = acc0;
        warp_sums[1][wid] = acc1;
    }
    __syncthreads();

    if (wid == 0 && lane < RPB * (TPB / 32)) {
        const int r = lane >> 3;
        const int w = lane & 7;
        float s = warp_sums[r][w];
        #pragma unroll
        for (int off = 4; off > 0; off >>= 1)
            s += __shfl_xor_sync(0xFFFFFFFFu, s, off);
        if (w == 0)
            y[row0 + r] = alpha[0] * s + beta[0] * b[row0 + r];
    }
}

extern "C" void kernel_launch(void* const* d_in, const int* in_sizes, int n_in,
                              void* d_out, int out_size) {
    const float* alpha = (const float*)d_in[0];
    const float* A     = (const float*)d_in[1];
    const float* x     = (const float*)d_in[2];
    const float* beta  = (const float*)d_in[3];
    const float* b     = (const float*)d_in[4];
    float* y = (float*)d_out;

    gemv_kernel<<<ROWS / RPB, TPB>>>(alpha, A, x, beta, b, y);
}

// round 8
// speedup vs baseline: 1.0400x; 1.0400x over previous
#include <cuda_runtime.h>

// GEMV: y = alpha * (A @ x) + beta * b
// A: [16384,16384] f32. Best structure (R6): 128-bit A loads, RPB=2,
// launch_bounds(256,8) -> 32 regs, ~100% occ. This round: unroll 4 to let
// ptxas front-batch more independent LDG.128s per thread (higher MLP).

#define ROWS 16384
#define COLS 16384
#define TPB  256
#define RPB  2

__global__ __launch_bounds__(TPB, 8) void gemv_kernel(
    const float* __restrict__ alpha,
    const float* __restrict__ A,
    const float* __restrict__ x,
    const float* __restrict__ beta,
    const float* __restrict__ b,
    float* __restrict__ y)
{
    const int row0 = blockIdx.x * RPB;
    const int tid  = threadIdx.x;

    const float4* __restrict__ r0 = reinterpret_cast<const float4*>(A + (size_t)row0 * COLS);
    const float4* __restrict__ r1 = reinterpret_cast<const float4*>(A + (size_t)(row0 + 1) * COLS);
    const float4* __restrict__ xv = reinterpret_cast<const float4*>(x);

    float acc0 = 0.0f, acc1 = 0.0f;

    // COLS/4 = 4096 float4; 256 threads -> 16 iterations each; unroll 4.
    #pragma unroll 4
    for (int i = tid; i < COLS / 4; i += TPB) {
        float4 a0 = __ldcs(&r0[i]);
        float4 a1 = __ldcs(&r1[i]);
        float4 v  = __ldg(&xv[i]);
        acc0 = fmaf(a0.x, v.x, acc0); acc0 = fmaf(a0.y, v.y, acc0);
        acc0 = fmaf(a0.z, v.z, acc0); acc0 = fmaf(a0.w, v.w, acc0);
        acc1 = fmaf(a1.x, v.x, acc1); acc1 = fmaf(a1.y, v.y, acc1);
        acc1 = fmaf(a1.z, v.z, acc1); acc1 = fmaf(a1.w, v.w, acc1);
    }

    // warp reduce both accumulators
    #pragma unroll
    for (int off = 16; off > 0; off >>= 1) {
        acc0 += __shfl_xor_sync(0xFFFFFFFFu, acc0, off);
        acc1 += __shfl_xor_sync(0xFFFFFFFFu, acc1, off);
    }

    __shared__ float warp_sums[RPB][TPB / 32];
    const int lane = tid & 31;
    const int wid  = tid >> 5;
    if (lane == 0) {
        warp_sums[0][wid] = acc0;
        warp_sums[1][wid] = acc1;
    }
    __syncthreads();

    // warp 0: lanes 0..15 cover 2 rows x 8 warp-sums
    if (wid == 0 && lane < RPB * (TPB / 32)) {
        const int r = lane >> 3;
        const int w = lane & 7;
        float s = warp_sums[r][w];
        #pragma unroll
        for (int off = 4; off > 0; off >>= 1)
            s += __shfl_xor_sync(0xFFFFFFFFu, s, off);
        if (w == 0)
            y[row0 + r] = alpha[0] * s + beta[0] * b[row0 + r];
    }
}

extern "C" void kernel_launch(void* const* d_in, const int* in_sizes, int n_in,
                              void* d_out, int out_size) {
    const float* alpha = (const float*)d_in[0];
    const float* A     = (const float*)d_in[1];
    const float* x     = (const float*)d_in[2];
    const float* beta  = (const float*)d_in[3];
    const float* b     = (const float*)d_in[4];
    float* y = (float*)d_out;

    gemv_kernel<<<ROWS / RPB, TPB>>>(alpha, A, x, beta, b, y);
}